// round 2
// baseline (speedup 1.0000x reference)
#include <cuda_runtime.h>
#include <cstdint>

#define D_MODEL 1024
#define BATCH   8
#define SEQ     2048
#define NROWS   (BATCH * SEQ)   // 16384

// ---------------- scratch (static device globals; no allocation) ----------------
__device__ float g_Q [(size_t)NROWS * D_MODEL];             // 64 MB
__device__ float g_K [(size_t)NROWS * D_MODEL];             // 64 MB
__device__ float g_Vt[(size_t)BATCH * D_MODEL * SEQ];       // 64 MB, [b][o][n]
__device__ float g_S [(size_t)BATCH * SEQ * SEQ];           // 128 MB

// ---------------- tf32 helpers ----------------
__device__ __forceinline__ float to_tf32(float x) {
    uint32_t u;
    asm("cvt.rna.tf32.f32 %0, %1;" : "=r"(u) : "f"(x));
    return __uint_as_float(u);
}

__device__ __forceinline__ void mma_tf32(float* c, const float* a, const float* b) {
    const uint32_t* A = reinterpret_cast<const uint32_t*>(a);
    const uint32_t* B = reinterpret_cast<const uint32_t*>(b);
    asm volatile(
        "mma.sync.aligned.m16n8k8.row.col.f32.tf32.tf32.f32 "
        "{%0,%1,%2,%3}, {%4,%5,%6,%7}, {%8,%9}, {%0,%1,%2,%3};\n"
        : "+f"(c[0]), "+f"(c[1]), "+f"(c[2]), "+f"(c[3])
        : "r"(A[0]), "r"(A[1]), "r"(A[2]), "r"(A[3]), "r"(B[0]), "r"(B[1]));
}

// ---------------- generic NT GEMM:  C = scale * A @ B^T ----------------
// A: [M,K] row-major, B: [N,K] row-major (C[m][n] = sum_k A[m][k]*B[n][k]).
// MODE 0: plain store
// MODE 1: transposed V store -> Vt[(b*D_MODEL + o)*SEQ + n]
// MODE 2: causal S gemm: skip tiles fully above the diagonal
// MODE 3: PV gemm: truncate K loop at m0+BM (P rows are zero beyond diagonal)
#define BM 128
#define BN 128
#define BK 16
#define KPAD 20   // conflict-free fragment reads (20*g mod 32 covers all banks)

template<int MODE>
__global__ void __launch_bounds__(256)
gemm_nt(const float* __restrict__ Ag, const float* __restrict__ Bg, float* __restrict__ Cg,
        int M, int N, int K,
        long long sA, long long sB, long long sC, float scale)
{
    const float* A = Ag + (size_t)blockIdx.z * sA;
    const float* B = Bg + (size_t)blockIdx.z * sB;
    float*       C = Cg + (size_t)blockIdx.z * sC;

    const int m0 = blockIdx.y * BM;
    const int n0 = blockIdx.x * BN;

    if (MODE == 2 && n0 > m0 + BM - 1) return;   // fully-masked causal tile
    const int kEnd = (MODE == 3) ? min(K, m0 + BM) : K;

    __shared__ float As[BM][KPAD];
    __shared__ float Bs[BN][KPAD];

    const int tid  = threadIdx.x;
    const int warp = tid >> 5;
    const int lane = tid & 31;
    const int g    = lane >> 2;   // groupID (row within m16n8 tile)
    const int tg   = lane & 3;    // thread-in-group
    const int wm   = (warp & 1) * 64;   // 2 warps along M
    const int wn   = (warp >> 1) * 32;  // 4 warps along N; warp tile 64x32

    // per-thread staging for the global->smem tiles (register double buffer)
    const int ld_row = tid >> 2;          // 0..63 (x2 with offset 64)
    const int ld_cb  = (tid & 3) << 2;    // 0,4,8,12

    float4 a_st[2], b_st[2];

    auto load_tile = [&](int k0) {
        #pragma unroll
        for (int i = 0; i < 2; i++) {
            int row = ld_row + i * 64;
            float4 a = *reinterpret_cast<const float4*>(A + (size_t)(m0 + row) * K + k0 + ld_cb);
            float4 b = *reinterpret_cast<const float4*>(B + (size_t)(n0 + row) * K + k0 + ld_cb);
            a_st[i] = make_float4(to_tf32(a.x), to_tf32(a.y), to_tf32(a.z), to_tf32(a.w));
            b_st[i] = make_float4(to_tf32(b.x), to_tf32(b.y), to_tf32(b.z), to_tf32(b.w));
        }
    };
    auto store_tile = [&]() {
        #pragma unroll
        for (int i = 0; i < 2; i++) {
            int row = ld_row + i * 64;
            *reinterpret_cast<float4*>(&As[row][ld_cb]) = a_st[i];
            *reinterpret_cast<float4*>(&Bs[row][ld_cb]) = b_st[i];
        }
    };

    float acc[4][4][4];
    #pragma unroll
    for (int i = 0; i < 4; i++)
        #pragma unroll
        for (int j = 0; j < 4; j++)
            #pragma unroll
            for (int r = 0; r < 4; r++) acc[i][j][r] = 0.f;

    load_tile(0);
    store_tile();
    __syncthreads();

    for (int k0 = 0; k0 < kEnd; k0 += BK) {
        const bool has_next = (k0 + BK) < kEnd;
        if (has_next) load_tile(k0 + BK);   // prefetch overlaps the MMAs below

        #pragma unroll
        for (int ks = 0; ks < BK / 8; ks++) {
            const int ko = ks * 8;
            float af[4][4], bf[4][2];
            #pragma unroll
            for (int mt = 0; mt < 4; mt++) {
                int r = wm + mt * 16 + g;
                af[mt][0] = As[r    ][ko + tg];
                af[mt][1] = As[r + 8][ko + tg];
                af[mt][2] = As[r    ][ko + tg + 4];
                af[mt][3] = As[r + 8][ko + tg + 4];
            }
            #pragma unroll
            for (int nt = 0; nt < 4; nt++) {
                int c = wn + nt * 8 + g;
                bf[nt][0] = Bs[c][ko + tg];
                bf[nt][1] = Bs[c][ko + tg + 4];
            }
            #pragma unroll
            for (int mt = 0; mt < 4; mt++)
                #pragma unroll
                for (int nt = 0; nt < 4; nt++)
                    mma_tf32(acc[mt][nt], af[mt], bf[nt]);
        }
        __syncthreads();
        if (has_next) {
            store_tile();
            __syncthreads();
        }
    }

    // ---- epilogue
    #pragma unroll
    for (int mt = 0; mt < 4; mt++) {
        const int r0 = m0 + wm + mt * 16 + g;
        #pragma unroll
        for (int nt = 0; nt < 4; nt++) {
            const int col = n0 + wn + nt * 8 + tg * 2;
            const float* a4 = acc[mt][nt];
            if (MODE == 1) {
                #pragma unroll
                for (int h = 0; h < 2; h++) {
                    int r = r0 + h * 8;
                    size_t base = ((size_t)(r >> 11) * D_MODEL) * SEQ + (size_t)(r & (SEQ - 1));
                    C[base + (size_t)(col    ) * SEQ] = a4[h * 2 + 0];
                    C[base + (size_t)(col + 1) * SEQ] = a4[h * 2 + 1];
                }
            } else {
                float2 v0 = make_float2(a4[0] * scale, a4[1] * scale);
                float2 v1 = make_float2(a4[2] * scale, a4[3] * scale);
                *reinterpret_cast<float2*>(C + (size_t)r0 * N + col)       = v0;
                *reinterpret_cast<float2*>(C + (size_t)(r0 + 8) * N + col) = v1;
            }
        }
    }
}

// ---------------- causal softmax, one block per row, in-place on S ----------------
__global__ void __launch_bounds__(256) softmax_causal(float* __restrict__ S)
{
    __shared__ float red[8];
    const int row = blockIdx.x;            // 0..NROWS-1
    const int i   = row & (SEQ - 1);       // query index within batch
    const int L   = i + 1;                 // valid length
    float* s = S + (size_t)row * SEQ;
    const int tid = threadIdx.x;

    float v[SEQ / 256];
    float m = -3.4e38f;
    #pragma unroll
    for (int it = 0; it < SEQ / 256; it++) {
        int j = tid + it * 256;
        v[it] = (j < L) ? s[j] : -3.4e38f;
        m = fmaxf(m, v[it]);
    }
    #pragma unroll
    for (int o = 16; o; o >>= 1) m = fmaxf(m, __shfl_xor_sync(0xffffffffu, m, o));
    if ((tid & 31) == 0) red[tid >> 5] = m;
    __syncthreads();
    m = red[0];
    #pragma unroll
    for (int w = 1; w < 8; w++) m = fmaxf(m, red[w]);
    __syncthreads();

    float sum = 0.f;
    #pragma unroll
    for (int it = 0; it < SEQ / 256; it++) {
        int j = tid + it * 256;
        float e = (j < L) ? __expf(v[it] - m) : 0.f;
        v[it] = e;
        sum += e;
    }
    #pragma unroll
    for (int o = 16; o; o >>= 1) sum += __shfl_xor_sync(0xffffffffu, sum, o);
    if ((tid & 31) == 0) red[tid >> 5] = sum;
    __syncthreads();
    sum = 0.f;
    #pragma unroll
    for (int w = 0; w < 8; w++) sum += red[w];
    const float inv = 1.f / sum;

    #pragma unroll
    for (int it = 0; it < SEQ / 256; it++) {
        int j = tid + it * 256;
        s[j] = v[it] * inv;   // exact zeros above the diagonal
    }
}

// ---------------- launch ----------------
extern "C" void kernel_launch(void* const* d_in, const int* in_sizes, int n_in,
                              void* d_out, int out_size)
{
    const float* x  = (const float*)d_in[0];
    const float* Wq = (const float*)d_in[1];
    const float* Wk = (const float*)d_in[2];
    const float* Wv = (const float*)d_in[3];
    float* out = (float*)d_out;

    float *pQ, *pK, *pVt, *pS;
    cudaGetSymbolAddress((void**)&pQ,  g_Q);
    cudaGetSymbolAddress((void**)&pK,  g_K);
    cudaGetSymbolAddress((void**)&pVt, g_Vt);
    cudaGetSymbolAddress((void**)&pS,  g_S);

    const dim3 blk(256);

    // 1) projections: [16384,1024] x [1024,1024]^T
    {
        dim3 grid(D_MODEL / BN, NROWS / BM, 1);
        gemm_nt<0><<<grid, blk>>>(x, Wq, pQ,  NROWS, D_MODEL, D_MODEL, 0, 0, 0, 1.f);
        gemm_nt<0><<<grid, blk>>>(x, Wk, pK,  NROWS, D_MODEL, D_MODEL, 0, 0, 0, 1.f);
        gemm_nt<1><<<grid, blk>>>(x, Wv, pVt, NROWS, D_MODEL, D_MODEL, 0, 0, 0, 1.f);
    }

    // 2) S = (Q @ K^T) / 32, batched, causal tile skip
    {
        dim3 grid(SEQ / BN, SEQ / BM, BATCH);
        gemm_nt<2><<<grid, blk>>>(pQ, pK, pS, SEQ, SEQ, D_MODEL,
                                  (long long)SEQ * D_MODEL,
                                  (long long)SEQ * D_MODEL,
                                  (long long)SEQ * SEQ, 0.03125f);
    }

    // 3) causal softmax in place (writes zeros above diagonal)
    softmax_causal<<<NROWS, blk>>>(pS);

    // 4) O = P @ Vt^T, batched, K-loop truncated per block-row
    {
        dim3 grid(D_MODEL / BN, SEQ / BM, BATCH);
        gemm_nt<3><<<grid, blk>>>(pS, pVt, out, SEQ, D_MODEL, SEQ,
                                  (long long)SEQ * SEQ,
                                  (long long)D_MODEL * SEQ,
                                  (long long)SEQ * D_MODEL, 1.f);
    }
}

// round 6
// speedup vs baseline: 2.1396x; 2.1396x over previous
#include <cuda_runtime.h>
#include <cuda_fp16.h>
#include <cstdint>

#define D_MODEL 1024
#define BATCH   8
#define SEQ     2048
#define NROWS   (BATCH * SEQ)   // 16384

// ---------------- scratch (static device globals; no allocation) ----------------
__device__ __half g_xh [(size_t)NROWS * D_MODEL];            // 32 MB
__device__ __half g_Wqh[(size_t)D_MODEL * D_MODEL];          // 2 MB
__device__ __half g_Wkh[(size_t)D_MODEL * D_MODEL];
__device__ __half g_Wvh[(size_t)D_MODEL * D_MODEL];
__device__ __half g_Qh [(size_t)NROWS * D_MODEL];            // 32 MB
__device__ __half g_Kh [(size_t)NROWS * D_MODEL];            // 32 MB
__device__ __half g_Vth[(size_t)BATCH * D_MODEL * SEQ];      // 32 MB, [b][o][tok]
__device__ float  g_S  [(size_t)BATCH * SEQ * SEQ];          // 128 MB
__device__ __half g_P  [(size_t)BATCH * SEQ * SEQ];          // 64 MB

// ---------------- tiling ----------------
#define BM 128
#define BN 256
#define BKH 32          // halves per k-tile
#define STAGES 4
#define ROW_B 80        // 32 halves data + 8 pad = 80 bytes/row
#define STAGE_A (BM * ROW_B)            // 10240
#define STAGE_B (BN * ROW_B)            // 20480
#define STAGE_BYTES (STAGE_A + STAGE_B) // 30720
#define SMEM_TOTAL (STAGES * STAGE_BYTES)  // 122880

// ---------------- ptx helpers ----------------
__device__ __forceinline__ uint32_t s2u(const void* p) {
    uint32_t a;
    asm("{ .reg .u64 t; cvta.to.shared.u64 t, %1; cvt.u32.u64 %0, t; }" : "=r"(a) : "l"(p));
    return a;
}
__device__ __forceinline__ void cp16(uint32_t dst, const void* src) {
    asm volatile("cp.async.cg.shared.global [%0], [%1], 16;" :: "r"(dst), "l"(src));
}
#define CP_COMMIT() asm volatile("cp.async.commit_group;" ::: "memory")
#define CP_WAIT(n)  asm volatile("cp.async.wait_group %0;" :: "n"(n) : "memory")

__device__ __forceinline__ void ldmx4(uint32_t* r, uint32_t a) {
    asm volatile("ldmatrix.sync.aligned.m8n8.x4.shared.b16 {%0,%1,%2,%3}, [%4];"
        : "=r"(r[0]), "=r"(r[1]), "=r"(r[2]), "=r"(r[3]) : "r"(a));
}
__device__ __forceinline__ void mma16816(float* c, const uint32_t* a, const uint32_t* b) {
    asm volatile(
        "mma.sync.aligned.m16n8k16.row.col.f32.f16.f16.f32 "
        "{%0,%1,%2,%3},{%4,%5,%6,%7},{%8,%9},{%0,%1,%2,%3};"
        : "+f"(c[0]), "+f"(c[1]), "+f"(c[2]), "+f"(c[3])
        : "r"(a[0]), "r"(a[1]), "r"(a[2]), "r"(a[3]), "r"(b[0]), "r"(b[1]));
}

// ---------------- fp16 NT GEMM:  C = scale * A @ B^T ----------------
// A: [M,K] halves row-major; B: [N,K] halves row-major.
// CTA 128x256, 512 threads (16 warps, 2M x 8N, warp tile 64x32), 4-stage cp.async.
// MODE 0: C fp16 plain   MODE 1: C fp16 transposed -> Vt[(b*D+o)*SEQ + tok]
// MODE 2: C fp32 * scale, causal tile skip
// MODE 3: C fp32, K truncated at m0+BM
template<int MODE>
__global__ void __launch_bounds__(512, 1)
gemm_h(const __half* __restrict__ Ag, const __half* __restrict__ Bg, void* __restrict__ Cv,
       int K_, int Ng, long long sA, long long sB, long long sC, float scale)
{
    extern __shared__ char smn[];
    const int m0 = blockIdx.y * BM;
    const int n0 = blockIdx.x * BN;
    if (MODE == 2 && n0 >= m0 + BM) return;

    const __half* A = Ag + (size_t)blockIdx.z * sA;
    const __half* B = Bg + (size_t)blockIdx.z * sB;

    const int kEnd = (MODE == 3) ? (m0 + BM) : K_;
    const int NT   = kEnd / BKH;

    const uint32_t sbase = s2u(smn);
    const int tid = threadIdx.x, wid = tid >> 5, lane = tid & 31;
    const int wm = (wid & 1) * 64;
    const int wn = (wid >> 1) * 32;
    const int g  = lane >> 2, tq = lane & 3;
    const int ld_r = tid >> 2, ld_c = tid & 3;     // loader row / 16B-chunk

    auto issue = [&](int kt) {
        if (kt < NT) {
            const uint32_t ab = sbase + (kt & 3) * STAGE_BYTES;
            const uint32_t bb = ab + STAGE_A;
            const int k0 = kt * BKH;
            cp16(ab + ld_r * ROW_B + ld_c * 16, A + (size_t)(m0 + ld_r) * K_ + k0 + ld_c * 8);
            cp16(bb + ld_r * ROW_B + ld_c * 16, B + (size_t)(n0 + ld_r) * K_ + k0 + ld_c * 8);
            cp16(bb + (ld_r + 128) * ROW_B + ld_c * 16,
                 B + (size_t)(n0 + ld_r + 128) * K_ + k0 + ld_c * 8);
        }
        CP_COMMIT();
    };

    #pragma unroll
    for (int s = 0; s < STAGES - 1; s++) issue(s);

    float acc[4][4][4];
    #pragma unroll
    for (int i = 0; i < 4; i++)
        #pragma unroll
        for (int j = 0; j < 4; j++)
            #pragma unroll
            for (int r = 0; r < 4; r++) acc[i][j][r] = 0.f;

    const int l7 = lane & 7, sel = lane >> 3;

    for (int kt = 0; kt < NT; kt++) {
        CP_WAIT(2);              // stage kt complete
        __syncthreads();
        issue(kt + STAGES - 1);  // refill slot (kt-1)&3 — everyone is done reading it

        const uint32_t ab = sbase + (kt & 3) * STAGE_BYTES;
        const uint32_t bb = ab + STAGE_A;
        #pragma unroll
        for (int ks = 0; ks < 2; ks++) {
            uint32_t af[4][4], bf[4][2];
            #pragma unroll
            for (int mt = 0; mt < 4; mt++) {
                int row = wm + mt * 16 + l7 + ((sel & 1) << 3);
                int ch  = ks * 2 + (sel >> 1);
                ldmx4(af[mt], ab + row * ROW_B + ch * 16);
            }
            #pragma unroll
            for (int p = 0; p < 2; p++) {
                int nrow = wn + p * 16 + ((sel >> 1) << 3) + l7;
                int ch   = ks * 2 + (sel & 1);
                uint32_t r[4];
                ldmx4(r, bb + nrow * ROW_B + ch * 16);
                bf[p * 2][0] = r[0]; bf[p * 2][1] = r[1];
                bf[p * 2 + 1][0] = r[2]; bf[p * 2 + 1][1] = r[3];
            }
            #pragma unroll
            for (int mt = 0; mt < 4; mt++)
                #pragma unroll
                for (int nt = 0; nt < 4; nt++)
                    mma16816(acc[mt][nt], af[mt], bf[nt]);
        }
    }

    // ---- epilogue ----
    if (MODE == 0) {
        __half* C = (__half*)Cv;
        #pragma unroll
        for (int mt = 0; mt < 4; mt++) {
            int r0 = m0 + wm + mt * 16 + g;
            #pragma unroll
            for (int nt = 0; nt < 4; nt++) {
                int c = n0 + wn + nt * 8 + tq * 2;
                *reinterpret_cast<__half2*>(C + (size_t)r0 * Ng + c) =
                    __floats2half2_rn(acc[mt][nt][0], acc[mt][nt][1]);
                *reinterpret_cast<__half2*>(C + (size_t)(r0 + 8) * Ng + c) =
                    __floats2half2_rn(acc[mt][nt][2], acc[mt][nt][3]);
            }
        }
    } else if (MODE == 1) {
        // drain pipeline before reusing smem, then per-warp transpose staging
        CP_WAIT(0);
        __syncthreads();
        __half* hbuf = reinterpret_cast<__half*>(smn + wid * 4608);  // [32 c][72] halves
        #pragma unroll
        for (int mt = 0; mt < 4; mt++) {
            int t0 = mt * 16 + g;
            #pragma unroll
            for (int nt = 0; nt < 4; nt++) {
                int c = nt * 8 + tq * 2;
                hbuf[(c    ) * 72 + t0    ] = __float2half_rn(acc[mt][nt][0]);
                hbuf[(c + 1) * 72 + t0    ] = __float2half_rn(acc[mt][nt][1]);
                hbuf[(c    ) * 72 + t0 + 8] = __float2half_rn(acc[mt][nt][2]);
                hbuf[(c + 1) * 72 + t0 + 8] = __float2half_rn(acc[mt][nt][3]);
            }
        }
        __syncwarp();
        {
            __half* C = (__half*)Cv;
            const int b = m0 >> 11, tok0 = (m0 & (SEQ - 1)) + wm;
            const int o = n0 + wn + lane;
            const uint4* src = reinterpret_cast<const uint4*>(hbuf + lane * 72);
            uint4* dst = reinterpret_cast<uint4*>(C + ((size_t)(b * D_MODEL + o)) * SEQ + tok0);
            #pragma unroll
            for (int u = 0; u < 8; u++) dst[u] = src[u];
        }
    } else {
        float* C = (float*)Cv + (size_t)blockIdx.z * sC;
        #pragma unroll
        for (int mt = 0; mt < 4; mt++) {
            int r0 = m0 + wm + mt * 16 + g;
            #pragma unroll
            for (int nt = 0; nt < 4; nt++) {
                int c = n0 + wn + nt * 8 + tq * 2;
                float2 v0 = make_float2(acc[mt][nt][0] * scale, acc[mt][nt][1] * scale);
                float2 v1 = make_float2(acc[mt][nt][2] * scale, acc[mt][nt][3] * scale);
                *reinterpret_cast<float2*>(C + (size_t)r0 * Ng + c) = v0;
                *reinterpret_cast<float2*>(C + (size_t)(r0 + 8) * Ng + c) = v1;
            }
        }
    }
}

// ---------------- fp32 -> fp16 conversion ----------------
__global__ void __launch_bounds__(256) f2h(const float4* __restrict__ s,
                                           __half2* __restrict__ d, int n4)
{
    int i = blockIdx.x * blockDim.x + threadIdx.x;
    if (i < n4) {
        float4 v = s[i];
        d[2 * i]     = __floats2half2_rn(v.x, v.y);
        d[2 * i + 1] = __floats2half2_rn(v.z, v.w);
    }
}

// ---------------- causal softmax: S fp32 -> P fp16 ----------------
__global__ void __launch_bounds__(256) softmax_causal(const float* __restrict__ S,
                                                      __half* __restrict__ P)
{
    __shared__ float red[8];
    const int row = blockIdx.x;
    const int i   = row & (SEQ - 1);
    const int L   = i + 1;
    const int Wl  = (i | 127) + 1;     // zero-fill to 128-block edge (PV reads no further)
    const float* s = S + (size_t)row * SEQ;
    __half* p = P + (size_t)row * SEQ;
    const int tid = threadIdx.x;

    float v[SEQ / 256];
    float m = -3.4e38f;
    #pragma unroll
    for (int it = 0; it < SEQ / 256; it++) {
        int j = tid + it * 256;
        v[it] = (j < L) ? s[j] : -3.4e38f;
        m = fmaxf(m, v[it]);
    }
    #pragma unroll
    for (int o = 16; o; o >>= 1) m = fmaxf(m, __shfl_xor_sync(0xffffffffu, m, o));
    if ((tid & 31) == 0) red[tid >> 5] = m;
    __syncthreads();
    m = red[0];
    #pragma unroll
    for (int w = 1; w < 8; w++) m = fmaxf(m, red[w]);
    __syncthreads();

    float sum = 0.f;
    #pragma unroll
    for (int it = 0; it < SEQ / 256; it++) {
        int j = tid + it * 256;
        float e = (j < L) ? __expf(v[it] - m) : 0.f;
        v[it] = e;
        sum += e;
    }
    #pragma unroll
    for (int o = 16; o; o >>= 1) sum += __shfl_xor_sync(0xffffffffu, sum, o);
    if ((tid & 31) == 0) red[tid >> 5] = sum;
    __syncthreads();
    sum = 0.f;
    #pragma unroll
    for (int w = 0; w < 8; w++) sum += red[w];
    const float inv = 1.f / sum;

    #pragma unroll
    for (int it = 0; it < SEQ / 256; it++) {
        int j = tid + it * 256;
        if (j < Wl) p[j] = __float2half_rn(v[it] * inv);
    }
}

// ---------------- launch ----------------
extern "C" void kernel_launch(void* const* d_in, const int* in_sizes, int n_in,
                              void* d_out, int out_size)
{
    const float* x  = (const float*)d_in[0];
    const float* Wq = (const float*)d_in[1];
    const float* Wk = (const float*)d_in[2];
    const float* Wv = (const float*)d_in[3];
    float* out = (float*)d_out;

    __half *pxh, *pWqh, *pWkh, *pWvh, *pQh, *pKh, *pVth, *pP;
    float *pS;
    cudaGetSymbolAddress((void**)&pxh,  g_xh);
    cudaGetSymbolAddress((void**)&pWqh, g_Wqh);
    cudaGetSymbolAddress((void**)&pWkh, g_Wkh);
    cudaGetSymbolAddress((void**)&pWvh, g_Wvh);
    cudaGetSymbolAddress((void**)&pQh,  g_Qh);
    cudaGetSymbolAddress((void**)&pKh,  g_Kh);
    cudaGetSymbolAddress((void**)&pVth, g_Vth);
    cudaGetSymbolAddress((void**)&pS,   g_S);
    cudaGetSymbolAddress((void**)&pP,   g_P);

    cudaFuncSetAttribute(gemm_h<0>, cudaFuncAttributeMaxDynamicSharedMemorySize, SMEM_TOTAL);
    cudaFuncSetAttribute(gemm_h<1>, cudaFuncAttributeMaxDynamicSharedMemorySize, SMEM_TOTAL);
    cudaFuncSetAttribute(gemm_h<2>, cudaFuncAttributeMaxDynamicSharedMemorySize, SMEM_TOTAL);
    cudaFuncSetAttribute(gemm_h<3>, cudaFuncAttributeMaxDynamicSharedMemorySize, SMEM_TOTAL);

    // 0) convert inputs to fp16
    {
        int n4 = NROWS * D_MODEL / 4;
        f2h<<<(n4 + 255) / 256, 256>>>((const float4*)x, (__half2*)pxh, n4);
        int w4 = D_MODEL * D_MODEL / 4;
        f2h<<<(w4 + 255) / 256, 256>>>((const float4*)Wq, (__half2*)pWqh, w4);
        f2h<<<(w4 + 255) / 256, 256>>>((const float4*)Wk, (__half2*)pWkh, w4);
        f2h<<<(w4 + 255) / 256, 256>>>((const float4*)Wv, (__half2*)pWvh, w4);
    }

    const dim3 blk(512);

    // 1) projections: [16384,1024] x [1024,1024]^T  (Q,K plain fp16; V transposed)
    {
        dim3 grid(D_MODEL / BN, NROWS / BM, 1);
        gemm_h<0><<<grid, blk, SMEM_TOTAL>>>(pxh, pWqh, pQh,  D_MODEL, D_MODEL, 0, 0, 0, 1.f);
        gemm_h<0><<<grid, blk, SMEM_TOTAL>>>(pxh, pWkh, pKh,  D_MODEL, D_MODEL, 0, 0, 0, 1.f);
        gemm_h<1><<<grid, blk, SMEM_TOTAL>>>(pxh, pWvh, pVth, D_MODEL, D_MODEL, 0, 0, 0, 1.f);
    }

    // 2) S = (Q @ K^T) / 32, batched, causal tile skip
    {
        dim3 grid(SEQ / BN, SEQ / BM, BATCH);
        gemm_h<2><<<grid, blk, SMEM_TOTAL>>>(pQh, pKh, pS, D_MODEL, SEQ,
                                             (long long)SEQ * D_MODEL,
                                             (long long)SEQ * D_MODEL,
                                             (long long)SEQ * SEQ, 0.03125f);
    }

    // 3) causal softmax: S fp32 -> P fp16
    softmax_causal<<<NROWS, 256>>>(pS, pP);

    // 4) O = P @ Vt^T, batched, K truncated per block-row
    {
        dim3 grid(D_MODEL / BN, SEQ / BM, BATCH);
        gemm_h<3><<<grid, blk, SMEM_TOTAL>>>(pP, pVth, out, SEQ, D_MODEL,
                                             (long long)SEQ * SEQ,
                                             (long long)D_MODEL * SEQ,
                                             (long long)SEQ * D_MODEL, 1.f);
    }
}

// round 7
// speedup vs baseline: 2.2939x; 1.0721x over previous
#include <cuda_runtime.h>
#include <cuda_fp16.h>
#include <cstdint>

#define D_MODEL 1024
#define BATCH   8
#define SEQ     2048
#define NROWS   (BATCH * SEQ)   // 16384

// ---------------- scratch (static device globals; no allocation) ----------------
__device__ __half g_xh [(size_t)NROWS * D_MODEL];            // 32 MB
__device__ __half g_Wh [(size_t)3 * D_MODEL * D_MODEL];      // 6 MB  [Wq;Wk;Wv]
__device__ __half g_Qh [(size_t)NROWS * D_MODEL];            // 32 MB
__device__ __half g_Kh [(size_t)NROWS * D_MODEL];            // 32 MB
__device__ __half g_Vth[(size_t)BATCH * D_MODEL * SEQ];      // 32 MB, [b][o][tok]
__device__ float  g_S  [(size_t)BATCH * SEQ * SEQ];          // 128 MB
__device__ __half g_P  [(size_t)BATCH * SEQ * SEQ];          // 64 MB

// ---------------- tiling ----------------
#define BM 128
#define BN 256
#define BKH 32          // halves per k-tile
#define STAGES 5
#define ROW_B 80        // 32 halves data + 8 pad = 80 bytes/row
#define STAGE_A (BM * ROW_B)            // 10240
#define STAGE_B (BN * ROW_B)            // 20480
#define STAGE_BYTES (STAGE_A + STAGE_B) // 30720
#define SMEM_TOTAL (STAGES * STAGE_BYTES)  // 153600

// ---------------- ptx helpers ----------------
__device__ __forceinline__ uint32_t s2u(const void* p) {
    uint32_t a;
    asm("{ .reg .u64 t; cvta.to.shared.u64 t, %1; cvt.u32.u64 %0, t; }" : "=r"(a) : "l"(p));
    return a;
}
__device__ __forceinline__ void cp16(uint32_t dst, const void* src) {
    asm volatile("cp.async.cg.shared.global [%0], [%1], 16;" :: "r"(dst), "l"(src));
}
#define CP_COMMIT() asm volatile("cp.async.commit_group;" ::: "memory")
#define CP_WAIT(n)  asm volatile("cp.async.wait_group %0;" :: "n"(n) : "memory")

__device__ __forceinline__ void ldmx4(uint32_t* r, uint32_t a) {
    asm volatile("ldmatrix.sync.aligned.m8n8.x4.shared.b16 {%0,%1,%2,%3}, [%4];"
        : "=r"(r[0]), "=r"(r[1]), "=r"(r[2]), "=r"(r[3]) : "r"(a));
}
__device__ __forceinline__ void mma16816(float* c, const uint32_t* a, const uint32_t* b) {
    asm volatile(
        "mma.sync.aligned.m16n8k16.row.col.f32.f16.f16.f32 "
        "{%0,%1,%2,%3},{%4,%5,%6,%7},{%8,%9},{%0,%1,%2,%3};"
        : "+f"(c[0]), "+f"(c[1]), "+f"(c[2]), "+f"(c[3])
        : "r"(a[0]), "r"(a[1]), "r"(a[2]), "r"(a[3]), "r"(b[0]), "r"(b[1]));
}

// ---------------- fp16 NT GEMM:  C = scale * A @ B^T ----------------
// A: [M,K] halves row-major; B: [N,K] halves row-major.
// CTA 128x256, 512 threads (16 warps, 2M x 8N, warp tile 64x32), 5-stage cp.async.
// MODE 4 (QKV): N=3072; sector n0>>10: 0 -> Qh plain, 1 -> Kh plain, 2 -> Vt transposed
// MODE 2: C fp32 * scale, causal tile skip
// MODE 3: C fp32, K truncated at m0+BM
template<int MODE>
__global__ void __launch_bounds__(512, 1)
gemm_h(const __half* __restrict__ Ag, const __half* __restrict__ Bg, void* __restrict__ Cv,
       int K_, int Ng, long long sA, long long sB, long long sC, float scale,
       __half* __restrict__ Cq, __half* __restrict__ Ck, __half* __restrict__ Cvt)
{
    extern __shared__ char smn[];
    const int m0 = blockIdx.y * BM;
    const int n0 = blockIdx.x * BN;
    if (MODE == 2 && n0 >= m0 + BM) return;

    const __half* A = Ag + (size_t)blockIdx.z * sA;
    const __half* B = Bg + (size_t)blockIdx.z * sB;

    const int kEnd = (MODE == 3) ? (m0 + BM) : K_;
    const int NT   = kEnd / BKH;

    const uint32_t sbase = s2u(smn);
    const int tid = threadIdx.x, wid = tid >> 5, lane = tid & 31;
    const int wm = (wid & 1) * 64;
    const int wn = (wid >> 1) * 32;
    const int g  = lane >> 2, tq = lane & 3;
    const int ld_r = tid >> 2, ld_c = tid & 3;     // loader row / 16B-chunk

    auto issue = [&](int kt) {
        if (kt < NT) {
            const uint32_t ab = sbase + (kt % STAGES) * STAGE_BYTES;
            const uint32_t bb = ab + STAGE_A;
            const int k0 = kt * BKH;
            cp16(ab + ld_r * ROW_B + ld_c * 16, A + (size_t)(m0 + ld_r) * K_ + k0 + ld_c * 8);
            cp16(bb + ld_r * ROW_B + ld_c * 16, B + (size_t)(n0 + ld_r) * K_ + k0 + ld_c * 8);
            cp16(bb + (ld_r + 128) * ROW_B + ld_c * 16,
                 B + (size_t)(n0 + ld_r + 128) * K_ + k0 + ld_c * 8);
        }
        CP_COMMIT();
    };

    #pragma unroll
    for (int s = 0; s < STAGES - 1; s++) issue(s);

    float acc[4][4][4];
    #pragma unroll
    for (int i = 0; i < 4; i++)
        #pragma unroll
        for (int j = 0; j < 4; j++)
            #pragma unroll
            for (int r = 0; r < 4; r++) acc[i][j][r] = 0.f;

    const int l7 = lane & 7, sel = lane >> 3;

    for (int kt = 0; kt < NT; kt++) {
        CP_WAIT(STAGES - 2);     // stage kt complete
        __syncthreads();
        issue(kt + STAGES - 1);  // refill slot (kt-1)%STAGES — all readers past it

        const uint32_t ab = sbase + (kt % STAGES) * STAGE_BYTES;
        const uint32_t bb = ab + STAGE_A;
        #pragma unroll
        for (int ks = 0; ks < 2; ks++) {
            uint32_t af[4][4], bf[4][2];
            #pragma unroll
            for (int mt = 0; mt < 4; mt++) {
                int row = wm + mt * 16 + l7 + ((sel & 1) << 3);
                int ch  = ks * 2 + (sel >> 1);
                ldmx4(af[mt], ab + row * ROW_B + ch * 16);
            }
            #pragma unroll
            for (int p = 0; p < 2; p++) {
                int nrow = wn + p * 16 + ((sel >> 1) << 3) + l7;
                int ch   = ks * 2 + (sel & 1);
                uint32_t r[4];
                ldmx4(r, bb + nrow * ROW_B + ch * 16);
                bf[p * 2][0] = r[0]; bf[p * 2][1] = r[1];
                bf[p * 2 + 1][0] = r[2]; bf[p * 2 + 1][1] = r[3];
            }
            #pragma unroll
            for (int mt = 0; mt < 4; mt++)
                #pragma unroll
                for (int nt = 0; nt < 4; nt++)
                    mma16816(acc[mt][nt], af[mt], bf[nt]);
        }
    }

    // ---- epilogue ----
    if (MODE == 4) {
        const int sector = n0 >> 10;          // 0:Q 1:K 2:V
        const int nc0 = n0 & 1023;            // col within sector
        if (sector < 2) {
            __half* C = sector ? Ck : Cq;
            #pragma unroll
            for (int mt = 0; mt < 4; mt++) {
                int r0 = m0 + wm + mt * 16 + g;
                #pragma unroll
                for (int nt = 0; nt < 4; nt++) {
                    int c = nc0 + wn + nt * 8 + tq * 2;
                    *reinterpret_cast<__half2*>(C + (size_t)r0 * D_MODEL + c) =
                        __floats2half2_rn(acc[mt][nt][0], acc[mt][nt][1]);
                    *reinterpret_cast<__half2*>(C + (size_t)(r0 + 8) * D_MODEL + c) =
                        __floats2half2_rn(acc[mt][nt][2], acc[mt][nt][3]);
                }
            }
        } else {
            // transposed store: Vt[(b*D + o)*SEQ + tok]
            CP_WAIT(0);
            __syncthreads();
            __half* hbuf = reinterpret_cast<__half*>(smn + wid * 4608);  // [32 c][72] halves
            #pragma unroll
            for (int mt = 0; mt < 4; mt++) {
                int t0 = mt * 16 + g;
                #pragma unroll
                for (int nt = 0; nt < 4; nt++) {
                    int c = nt * 8 + tq * 2;
                    hbuf[(c    ) * 72 + t0    ] = __float2half_rn(acc[mt][nt][0]);
                    hbuf[(c + 1) * 72 + t0    ] = __float2half_rn(acc[mt][nt][1]);
                    hbuf[(c    ) * 72 + t0 + 8] = __float2half_rn(acc[mt][nt][2]);
                    hbuf[(c + 1) * 72 + t0 + 8] = __float2half_rn(acc[mt][nt][3]);
                }
            }
            __syncwarp();
            {
                const int b = m0 >> 11, tok0 = (m0 & (SEQ - 1)) + wm;
                const int o = nc0 + wn + lane;
                const uint4* src = reinterpret_cast<const uint4*>(hbuf + lane * 72);
                uint4* dst = reinterpret_cast<uint4*>(Cvt + ((size_t)(b * D_MODEL + o)) * SEQ + tok0);
                #pragma unroll
                for (int u = 0; u < 8; u++) dst[u] = src[u];
            }
        }
    } else {
        float* C = (float*)Cv + (size_t)blockIdx.z * sC;
        #pragma unroll
        for (int mt = 0; mt < 4; mt++) {
            int r0 = m0 + wm + mt * 16 + g;
            #pragma unroll
            for (int nt = 0; nt < 4; nt++) {
                int c = n0 + wn + nt * 8 + tq * 2;
                float2 v0 = make_float2(acc[mt][nt][0] * scale, acc[mt][nt][1] * scale);
                float2 v1 = make_float2(acc[mt][nt][2] * scale, acc[mt][nt][3] * scale);
                *reinterpret_cast<float2*>(C + (size_t)r0 * Ng + c) = v0;
                *reinterpret_cast<float2*>(C + (size_t)(r0 + 8) * Ng + c) = v1;
            }
        }
    }
}

// ---------------- fp32 -> fp16 conversion ----------------
__global__ void __launch_bounds__(256) f2h(const float4* __restrict__ s,
                                           __half2* __restrict__ d, int n4)
{
    int i = blockIdx.x * blockDim.x + threadIdx.x;
    if (i < n4) {
        float4 v = s[i];
        d[2 * i]     = __floats2half2_rn(v.x, v.y);
        d[2 * i + 1] = __floats2half2_rn(v.z, v.w);
    }
}

// ---------------- causal softmax: S fp32 -> P fp16 ----------------
__global__ void __launch_bounds__(256) softmax_causal(const float* __restrict__ S,
                                                      __half* __restrict__ P)
{
    __shared__ float red[8];
    const int row = blockIdx.x;
    const int i   = row & (SEQ - 1);
    const int L   = i + 1;
    const int Wl  = (i | 127) + 1;     // zero-fill to 128-block edge (PV reads no further)
    const float* s = S + (size_t)row * SEQ;
    __half* p = P + (size_t)row * SEQ;
    const int tid = threadIdx.x;

    float v[SEQ / 256];
    float m = -3.4e38f;
    #pragma unroll
    for (int it = 0; it < SEQ / 256; it++) {
        int j = tid + it * 256;
        v[it] = (j < L) ? s[j] : -3.4e38f;
        m = fmaxf(m, v[it]);
    }
    #pragma unroll
    for (int o = 16; o; o >>= 1) m = fmaxf(m, __shfl_xor_sync(0xffffffffu, m, o));
    if ((tid & 31) == 0) red[tid >> 5] = m;
    __syncthreads();
    m = red[0];
    #pragma unroll
    for (int w = 1; w < 8; w++) m = fmaxf(m, red[w]);
    __syncthreads();

    float sum = 0.f;
    #pragma unroll
    for (int it = 0; it < SEQ / 256; it++) {
        int j = tid + it * 256;
        float e = (j < L) ? __expf(v[it] - m) : 0.f;
        v[it] = e;
        sum += e;
    }
    #pragma unroll
    for (int o = 16; o; o >>= 1) sum += __shfl_xor_sync(0xffffffffu, sum, o);
    if ((tid & 31) == 0) red[tid >> 5] = sum;
    __syncthreads();
    sum = 0.f;
    #pragma unroll
    for (int w = 0; w < 8; w++) sum += red[w];
    const float inv = 1.f / sum;

    #pragma unroll
    for (int it = 0; it < SEQ / 256; it++) {
        int j = tid + it * 256;
        if (j < Wl) p[j] = __float2half_rn(v[it] * inv);
    }
}

// ---------------- launch ----------------
extern "C" void kernel_launch(void* const* d_in, const int* in_sizes, int n_in,
                              void* d_out, int out_size)
{
    const float* x  = (const float*)d_in[0];
    const float* Wq = (const float*)d_in[1];
    const float* Wk = (const float*)d_in[2];
    const float* Wv = (const float*)d_in[3];
    float* out = (float*)d_out;

    __half *pxh, *pWh, *pQh, *pKh, *pVth, *pP;
    float *pS;
    cudaGetSymbolAddress((void**)&pxh,  g_xh);
    cudaGetSymbolAddress((void**)&pWh,  g_Wh);
    cudaGetSymbolAddress((void**)&pQh,  g_Qh);
    cudaGetSymbolAddress((void**)&pKh,  g_Kh);
    cudaGetSymbolAddress((void**)&pVth, g_Vth);
    cudaGetSymbolAddress((void**)&pS,   g_S);
    cudaGetSymbolAddress((void**)&pP,   g_P);

    cudaFuncSetAttribute(gemm_h<4>, cudaFuncAttributeMaxDynamicSharedMemorySize, SMEM_TOTAL);
    cudaFuncSetAttribute(gemm_h<2>, cudaFuncAttributeMaxDynamicSharedMemorySize, SMEM_TOTAL);
    cudaFuncSetAttribute(gemm_h<3>, cudaFuncAttributeMaxDynamicSharedMemorySize, SMEM_TOTAL);

    const int WSZ = D_MODEL * D_MODEL;   // one weight matrix

    // 0) convert inputs to fp16 (launches 0-3)
    {
        int n4 = NROWS * D_MODEL / 4;
        f2h<<<(n4 + 255) / 256, 256>>>((const float4*)x, (__half2*)pxh, n4);
        int w4 = WSZ / 4;
        f2h<<<(w4 + 255) / 256, 256>>>((const float4*)Wq, (__half2*)pWh, w4);
        f2h<<<(w4 + 255) / 256, 256>>>((const float4*)Wk, (__half2*)(pWh + WSZ), w4);
        f2h<<<(w4 + 255) / 256, 256>>>((const float4*)Wv, (__half2*)(pWh + 2 * WSZ), w4);
    }

    const dim3 blk(512);

    // 1) fused QKV projection: [16384,1024] x [3072,1024]^T  (launch 4)
    {
        dim3 grid(3 * D_MODEL / BN, NROWS / BM, 1);
        gemm_h<4><<<grid, blk, SMEM_TOTAL>>>(pxh, pWh, nullptr, D_MODEL, 3 * D_MODEL,
                                             0, 0, 0, 1.f, pQh, pKh, pVth);
    }

    // 2) S = (Q @ K^T) / 32, batched, causal tile skip  (launch 5 — ncu target)
    {
        dim3 grid(SEQ / BN, SEQ / BM, BATCH);
        gemm_h<2><<<grid, blk, SMEM_TOTAL>>>(pQh, pKh, pS, D_MODEL, SEQ,
                                             (long long)SEQ * D_MODEL,
                                             (long long)SEQ * D_MODEL,
                                             (long long)SEQ * SEQ, 0.03125f,
                                             nullptr, nullptr, nullptr);
    }

    // 3) causal softmax: S fp32 -> P fp16
    softmax_causal<<<NROWS, 256>>>(pS, pP);

    // 4) O = P @ Vt^T, batched, K truncated per block-row
    {
        dim3 grid(D_MODEL / BN, SEQ / BM, BATCH);
        gemm_h<3><<<grid, blk, SMEM_TOTAL>>>(pP, pVth, out, SEQ, D_MODEL,
                                             (long long)SEQ * SEQ,
                                             (long long)D_MODEL * SEQ,
                                             (long long)SEQ * D_MODEL, 1.f,
                                             nullptr, nullptr, nullptr);
    }
}

// round 10
// speedup vs baseline: 2.6354x; 1.1488x over previous
#include <cuda_runtime.h>
#include <cuda_fp16.h>
#include <cstdint>

#define D_MODEL 1024
#define BATCH   8
#define SEQ     2048
#define NROWS   (BATCH * SEQ)   // 16384

// ---------------- scratch (static device globals; no allocation) ----------------
__device__ __half g_xh [(size_t)NROWS * D_MODEL];            // 32 MB
__device__ __half g_Wh [(size_t)3 * D_MODEL * D_MODEL];      // 6 MB  [Wq;Wk;Wv]
__device__ __half g_Qh [(size_t)NROWS * D_MODEL];            // 32 MB
__device__ __half g_Kh [(size_t)NROWS * D_MODEL];            // 32 MB
__device__ __half g_Vth[(size_t)BATCH * D_MODEL * SEQ];      // 32 MB, [b][o][tok]
__device__ float  g_S  [(size_t)BATCH * SEQ * SEQ];          // 128 MB
__device__ __half g_P  [(size_t)BATCH * SEQ * SEQ];          // 64 MB

// ---------------- tiling: 128x128 CTA, 256 threads, 2 CTAs/SM ----------------
#define BM 128
#define BN 128
#define BKH 32          // halves per k-tile
#define STAGES 4
#define ROW_B 80        // 64B data + 16B pad per row (conflict-free ldmatrix)
#define STAGE_A (BM * ROW_B)            // 10240
#define STAGE_B (BN * ROW_B)            // 10240
#define STAGE_BYTES (STAGE_A + STAGE_B) // 20480
#define SMEM_TOTAL (STAGES * STAGE_BYTES)  // 81920 -> 2 CTAs/SM

// ---------------- ptx helpers ----------------
__device__ __forceinline__ uint32_t s2u(const void* p) {
    uint32_t a;
    asm("{ .reg .u64 t; cvta.to.shared.u64 t, %1; cvt.u32.u64 %0, t; }" : "=r"(a) : "l"(p));
    return a;
}
__device__ __forceinline__ void cp16(uint32_t dst, const void* src) {
    asm volatile("cp.async.cg.shared.global [%0], [%1], 16;" :: "r"(dst), "l"(src));
}
#define CP_COMMIT() asm volatile("cp.async.commit_group;" ::: "memory")
#define CP_WAIT(n)  asm volatile("cp.async.wait_group %0;" :: "n"(n) : "memory")

__device__ __forceinline__ void ldmx4(uint32_t* r, uint32_t a) {
    asm volatile("ldmatrix.sync.aligned.m8n8.x4.shared.b16 {%0,%1,%2,%3}, [%4];"
        : "=r"(r[0]), "=r"(r[1]), "=r"(r[2]), "=r"(r[3]) : "r"(a));
}
__device__ __forceinline__ void mma16816(float* c, const uint32_t* a, const uint32_t* b) {
    asm volatile(
        "mma.sync.aligned.m16n8k16.row.col.f32.f16.f16.f32 "
        "{%0,%1,%2,%3},{%4,%5,%6,%7},{%8,%9},{%0,%1,%2,%3};"
        : "+f"(c[0]), "+f"(c[1]), "+f"(c[2]), "+f"(c[3])
        : "r"(a[0]), "r"(a[1]), "r"(a[2]), "r"(a[3]), "r"(b[0]), "r"(b[1]));
}

// ---------------- fp16 NT GEMM:  C = scale * A @ B^T ----------------
// A: [M,K] halves row-major; B: [N,K] halves row-major.
// CTA 128x128, 256 threads (8 warps = 2M x 4N, warp tile 64x32), 4-stage cp.async.
// MODE 4 (QKV): N=3072; sector n0>>10: 0 -> Qh plain, 1 -> Kh plain, 2 -> Vt transposed
// MODE 2: C fp32 * scale, causal tile skip
// MODE 3: C fp32, K truncated at m0+BM
template<int MODE>
__global__ void __launch_bounds__(256, 2)
gemm_h(const __half* __restrict__ Ag, const __half* __restrict__ Bg, void* __restrict__ Cv,
       int K_, int Ng, long long sA, long long sB, long long sC, float scale,
       __half* __restrict__ Cq, __half* __restrict__ Ck, __half* __restrict__ Cvt)
{
    extern __shared__ char smem_raw[];
    const int m0 = blockIdx.y * BM;
    const int n0 = blockIdx.x * BN;
    if (MODE == 2 && n0 >= m0 + BM) return;

    const __half* A = Ag + (size_t)blockIdx.z * sA;
    const __half* B = Bg + (size_t)blockIdx.z * sB;

    const int kEnd = (MODE == 3) ? (m0 + BM) : K_;
    const int NT   = kEnd / BKH;

    const uint32_t sbase = s2u(smem_raw);
    const int tid = threadIdx.x;
    const int wid = tid >> 5;
    const int lane = tid & 31;
    const int wm = (wid & 1) * 64;      // 2 warps along M
    const int wn = (wid >> 1) * 32;     // 4 warps along N
    const int g  = lane >> 2;
    const int tq = lane & 3;
    const int ld_r = tid >> 2;          // loader row (0..63)
    const int ld_c = (tid & 3) * 16;    // loader byte offset within row
    const int ld_k = (tid & 3) * 8;     // loader element offset within row

    auto issue = [&](int kt) {
        if (kt < NT) {
            const uint32_t stage = sbase + (kt % STAGES) * STAGE_BYTES;
            const size_t kcol = (size_t)(kt * BKH + ld_k);
            const __half* pa = A + (size_t)(m0 + ld_r) * K_ + kcol;
            const __half* pb = B + (size_t)(n0 + ld_r) * K_ + kcol;
            cp16(stage + ld_r * ROW_B + ld_c, pa);
            cp16(stage + STAGE_A + ld_r * ROW_B + ld_c, pb);
            cp16(stage + (ld_r + 64) * ROW_B + ld_c, pa + (size_t)64 * K_);
            cp16(stage + STAGE_A + (ld_r + 64) * ROW_B + ld_c, pb + (size_t)64 * K_);
        }
        CP_COMMIT();
    };

    issue(0);
    issue(1);
    issue(2);

    float acc[4][4][4];
    #pragma unroll
    for (int i = 0; i < 4; i++)
        #pragma unroll
        for (int j = 0; j < 4; j++)
            #pragma unroll
            for (int r = 0; r < 4; r++) acc[i][j][r] = 0.f;

    const int l7 = lane & 7, sel = lane >> 3;

    for (int kt = 0; kt < NT; kt++) {
        CP_WAIT(STAGES - 2);     // stage kt resident
        __syncthreads();
        issue(kt + STAGES - 1);  // refill slot (kt-1)%STAGES — all readers past it

        const uint32_t ab = sbase + (kt % STAGES) * STAGE_BYTES;
        const uint32_t bb = ab + STAGE_A;
        #pragma unroll
        for (int ks = 0; ks < 2; ks++) {
            uint32_t af[4][4], bf[4][2];
            #pragma unroll
            for (int mt = 0; mt < 4; mt++) {
                int row = wm + mt * 16 + l7 + ((sel & 1) << 3);
                int ch  = ks * 2 + (sel >> 1);
                ldmx4(af[mt], ab + row * ROW_B + ch * 16);
            }
            #pragma unroll
            for (int p = 0; p < 2; p++) {
                int nrow = wn + p * 16 + ((sel >> 1) << 3) + l7;
                int ch   = ks * 2 + (sel & 1);
                uint32_t r[4];
                ldmx4(r, bb + nrow * ROW_B + ch * 16);
                bf[p * 2][0] = r[0]; bf[p * 2][1] = r[1];
                bf[p * 2 + 1][0] = r[2]; bf[p * 2 + 1][1] = r[3];
            }
            #pragma unroll
            for (int mt = 0; mt < 4; mt++)
                #pragma unroll
                for (int nt = 0; nt < 4; nt++)
                    mma16816(acc[mt][nt], af[mt], bf[nt]);
        }
    }

    // ---- epilogue ----
    if (MODE == 4) {
        const int sector = n0 >> 10;          // 0:Q 1:K 2:V
        const int nc0 = n0 & 1023;            // col within sector
        if (sector < 2) {
            __half* C = sector ? Ck : Cq;
            #pragma unroll
            for (int mt = 0; mt < 4; mt++) {
                int r0 = m0 + wm + mt * 16 + g;
                #pragma unroll
                for (int nt = 0; nt < 4; nt++) {
                    int c = nc0 + wn + nt * 8 + tq * 2;
                    *reinterpret_cast<__half2*>(C + (size_t)r0 * D_MODEL + c) =
                        __floats2half2_rn(acc[mt][nt][0], acc[mt][nt][1]);
                    *reinterpret_cast<__half2*>(C + (size_t)(r0 + 8) * D_MODEL + c) =
                        __floats2half2_rn(acc[mt][nt][2], acc[mt][nt][3]);
                }
            }
        } else {
            // transposed store: Vt[(b*D + o)*SEQ + tok]
            CP_WAIT(0);
            __syncthreads();
            __half* hbuf = reinterpret_cast<__half*>(smem_raw + wid * 4608);  // [32 c][72]
            #pragma unroll
            for (int mt = 0; mt < 4; mt++) {
                int t0 = mt * 16 + g;
                #pragma unroll
                for (int nt = 0; nt < 4; nt++) {
                    int c = nt * 8 + tq * 2;
                    hbuf[(c    ) * 72 + t0    ] = __float2half_rn(acc[mt][nt][0]);
                    hbuf[(c + 1) * 72 + t0    ] = __float2half_rn(acc[mt][nt][1]);
                    hbuf[(c    ) * 72 + t0 + 8] = __float2half_rn(acc[mt][nt][2]);
                    hbuf[(c + 1) * 72 + t0 + 8] = __float2half_rn(acc[mt][nt][3]);
                }
            }
            __syncwarp();
            {
                const int b = m0 >> 11, tok0 = (m0 & (SEQ - 1)) + wm;
                const int o = nc0 + wn + lane;
                const uint4* src = reinterpret_cast<const uint4*>(hbuf + lane * 72);
                uint4* dst = reinterpret_cast<uint4*>(Cvt + ((size_t)(b * D_MODEL + o)) * SEQ + tok0);
                #pragma unroll
                for (int u = 0; u < 8; u++) dst[u] = src[u];
            }
        }
    } else {
        float* C = (float*)Cv + (size_t)blockIdx.z * sC;
        #pragma unroll
        for (int mt = 0; mt < 4; mt++) {
            int r0 = m0 + wm + mt * 16 + g;
            #pragma unroll
            for (int nt = 0; nt < 4; nt++) {
                int c = n0 + wn + nt * 8 + tq * 2;
                float2 v0 = make_float2(acc[mt][nt][0] * scale, acc[mt][nt][1] * scale);
                float2 v1 = make_float2(acc[mt][nt][2] * scale, acc[mt][nt][3] * scale);
                *reinterpret_cast<float2*>(C + (size_t)r0 * Ng + c) = v0;
                *reinterpret_cast<float2*>(C + (size_t)(r0 + 8) * Ng + c) = v1;
            }
        }
    }
}

// ---------------- fp32 -> fp16 conversion ----------------
__global__ void __launch_bounds__(256) f2h(const float4* __restrict__ s,
                                           __half2* __restrict__ d, int n4)
{
    int i = blockIdx.x * blockDim.x + threadIdx.x;
    if (i < n4) {
        float4 v = s[i];
        d[2 * i]     = __floats2half2_rn(v.x, v.y);
        d[2 * i + 1] = __floats2half2_rn(v.z, v.w);
    }
}

// ---------------- causal softmax: S fp32 -> P fp16 ----------------
__global__ void __launch_bounds__(256) softmax_causal(const float* __restrict__ S,
                                                      __half* __restrict__ P)
{
    __shared__ float red[8];
    const int row = blockIdx.x;
    const int i   = row & (SEQ - 1);
    const int L   = i + 1;
    const int Wl  = (i | 127) + 1;     // zero-fill to 128-block edge (PV reads no further)
    const float* s = S + (size_t)row * SEQ;
    __half* p = P + (size_t)row * SEQ;
    const int tid = threadIdx.x;

    float v[SEQ / 256];
    float m = -3.4e38f;
    #pragma unroll
    for (int it = 0; it < SEQ / 256; it++) {
        int j = tid + it * 256;
        v[it] = (j < L) ? s[j] : -3.4e38f;
        m = fmaxf(m, v[it]);
    }
    #pragma unroll
    for (int o = 16; o; o >>= 1) m = fmaxf(m, __shfl_xor_sync(0xffffffffu, m, o));
    if ((tid & 31) == 0) red[tid >> 5] = m;
    __syncthreads();
    m = red[0];
    #pragma unroll
    for (int w = 1; w < 8; w++) m = fmaxf(m, red[w]);
    __syncthreads();

    float sum = 0.f;
    #pragma unroll
    for (int it = 0; it < SEQ / 256; it++) {
        int j = tid + it * 256;
        float e = (j < L) ? __expf(v[it] - m) : 0.f;
        v[it] = e;
        sum += e;
    }
    #pragma unroll
    for (int o = 16; o; o >>= 1) sum += __shfl_xor_sync(0xffffffffu, sum, o);
    if ((tid & 31) == 0) red[tid >> 5] = sum;
    __syncthreads();
    sum = 0.f;
    #pragma unroll
    for (int w = 0; w < 8; w++) sum += red[w];
    const float inv = 1.f / sum;

    #pragma unroll
    for (int it = 0; it < SEQ / 256; it++) {
        int j = tid + it * 256;
        if (j < Wl) p[j] = __float2half_rn(v[it] * inv);
    }
}

// ---------------- launch ----------------
extern "C" void kernel_launch(void* const* d_in, const int* in_sizes, int n_in,
                              void* d_out, int out_size)
{
    const float* x  = (const float*)d_in[0];
    const float* Wq = (const float*)d_in[1];
    const float* Wk = (const float*)d_in[2];
    const float* Wv = (const float*)d_in[3];
    float* out = (float*)d_out;

    __half *pxh, *pWh, *pQh, *pKh, *pVth, *pP;
    float *pS;
    cudaGetSymbolAddress((void**)&pxh,  g_xh);
    cudaGetSymbolAddress((void**)&pWh,  g_Wh);
    cudaGetSymbolAddress((void**)&pQh,  g_Qh);
    cudaGetSymbolAddress((void**)&pKh,  g_Kh);
    cudaGetSymbolAddress((void**)&pVth, g_Vth);
    cudaGetSymbolAddress((void**)&pS,   g_S);
    cudaGetSymbolAddress((void**)&pP,   g_P);

    cudaFuncSetAttribute(gemm_h<4>, cudaFuncAttributeMaxDynamicSharedMemorySize, SMEM_TOTAL);
    cudaFuncSetAttribute(gemm_h<2>, cudaFuncAttributeMaxDynamicSharedMemorySize, SMEM_TOTAL);
    cudaFuncSetAttribute(gemm_h<3>, cudaFuncAttributeMaxDynamicSharedMemorySize, SMEM_TOTAL);

    const int WSZ = D_MODEL * D_MODEL;   // one weight matrix

    // 0) convert inputs to fp16
    {
        int n4 = NROWS * D_MODEL / 4;
        int w4 = WSZ / 4;
        f2h<<<(n4 + 255) / 256, 256>>>((const float4*)x, (__half2*)pxh, n4);
        f2h<<<(w4 + 255) / 256, 256>>>((const float4*)Wq, (__half2*)pWh, w4);
        f2h<<<(w4 + 255) / 256, 256>>>((const float4*)Wk, (__half2*)(pWh + WSZ), w4);
        f2h<<<(w4 + 255) / 256, 256>>>((const float4*)Wv, (__half2*)(pWh + 2 * WSZ), w4);
    }

    const dim3 blk(256);

    // 1) fused QKV projection: [16384,1024] x [3072,1024]^T
    {
        dim3 grid(3 * D_MODEL / BN, NROWS / BM, 1);
        gemm_h<4><<<grid, blk, SMEM_TOTAL>>>(pxh, pWh, nullptr, D_MODEL, 3 * D_MODEL,
                                             0, 0, 0, 1.f, pQh, pKh, pVth);
    }

    // 2) S = (Q @ K^T) / 32, batched, causal tile skip
    {
        dim3 grid(SEQ / BN, SEQ / BM, BATCH);
        gemm_h<2><<<grid, blk, SMEM_TOTAL>>>(pQh, pKh, pS, D_MODEL, SEQ,
                                             (long long)SEQ * D_MODEL,
                                             (long long)SEQ * D_MODEL,
                                             (long long)SEQ * SEQ, 0.03125f,
                                             nullptr, nullptr, nullptr);
    }

    // 3) causal softmax: S fp32 -> P fp16
    softmax_causal<<<NROWS, 256>>>(pS, pP);

    // 4) O = P @ Vt^T, batched, K truncated per block-row
    {
        dim3 grid(D_MODEL / BN, SEQ / BM, BATCH);
        gemm_h<3><<<grid, blk, SMEM_TOTAL>>>(pP, pVth, out, SEQ, D_MODEL,
                                             (long long)SEQ * SEQ,
                                             (long long)D_MODEL * SEQ,
                                             (long long)SEQ * D_MODEL, 1.f,
                                             nullptr, nullptr, nullptr);
    }
}

// round 12
// speedup vs baseline: 2.8021x; 1.0633x over previous
#include <cuda_runtime.h>
#include <cuda_fp16.h>
#include <cstdint>

#define D_MODEL 1024
#define BATCH   8
#define SEQ     2048
#define NROWS   (BATCH * SEQ)   /* 16384 rows total */

// ---------------- scratch (static device globals; no allocation) ----------------
__device__ __half g_xh [(size_t)NROWS * D_MODEL];
__device__ __half g_Wh [(size_t)3 * D_MODEL * D_MODEL];      // [Wq;Wk;Wv]
__device__ __half g_Qh [(size_t)NROWS * D_MODEL];
__device__ __half g_Kh [(size_t)NROWS * D_MODEL];
__device__ __half g_Vth[(size_t)BATCH * D_MODEL * SEQ];      // [b][o][tok]
__device__ float  g_S  [(size_t)BATCH * SEQ * SEQ];
__device__ __half g_P  [(size_t)BATCH * SEQ * SEQ];

// -------- tiling: 128x128 CTA, 256 threads, 2 CTAs/SM, 64-half k-tiles --------
#define BM 128
#define BN 128
#define BKH 64
#define STAGES 3
#define ROW_B 144       /* 128B data + 16B pad; 36-bank stride -> conflict-free */
#define STAGE_A (BM * ROW_B)
#define STAGE_B (BN * ROW_B)
#define STAGE_BYTES (STAGE_A + STAGE_B)
#define SMEM_TOTAL (STAGES * STAGE_BYTES)   /* 110592 B -> 2 CTAs/SM */

// ---------------- ptx helpers ----------------
__device__ __forceinline__ uint32_t s2u(const void* p) {
    uint32_t a;
    asm("{ .reg .u64 t; cvta.to.shared.u64 t, %1; cvt.u32.u64 %0, t; }" : "=r"(a) : "l"(p));
    return a;
}
__device__ __forceinline__ void cp16(uint32_t dst, const void* src) {
    asm volatile("cp.async.cg.shared.global [%0], [%1], 16;" :: "r"(dst), "l"(src));
}
#define CP_COMMIT() asm volatile("cp.async.commit_group;" ::: "memory")
#define CP_WAIT(n)  asm volatile("cp.async.wait_group %0;" :: "n"(n) : "memory")

__device__ __forceinline__ void ldmx4(uint32_t* r, uint32_t a) {
    asm volatile("ldmatrix.sync.aligned.m8n8.x4.shared.b16 {%0,%1,%2,%3}, [%4];"
        : "=r"(r[0]), "=r"(r[1]), "=r"(r[2]), "=r"(r[3]) : "r"(a));
}
__device__ __forceinline__ void mma16816(float* c, const uint32_t* a, const uint32_t* b) {
    asm volatile(
        "mma.sync.aligned.m16n8k16.row.col.f32.f16.f16.f32 "
        "{%0,%1,%2,%3},{%4,%5,%6,%7},{%8,%9},{%0,%1,%2,%3};"
        : "+f"(c[0]), "+f"(c[1]), "+f"(c[2]), "+f"(c[3])
        : "r"(a[0]), "r"(a[1]), "r"(a[2]), "r"(a[3]), "r"(b[0]), "r"(b[1]));
}

// ---------------- fp16 NT GEMM:  C = scale * A @ B^T ----------------
// Modes: 4 = fused QKV (N=3072, sector-routed epilogue, V transposed)
//        2 = S gemm (fp32 out * scale, causal tile skip)
//        3 = PV gemm (fp32 out, K truncated at m0+BM, longest m-tiles first)
template<int MODE>
__global__ void __launch_bounds__(256, 2)
gemm_h(const __half* __restrict__ Ag, const __half* __restrict__ Bg, void* __restrict__ Cv,
       int K_, int Ng, long long sA, long long sB, long long sC, float scale,
       __half* __restrict__ Cq, __half* __restrict__ Ck, __half* __restrict__ Cvt)
{
    extern __shared__ char smem_raw[];
    const int my = (MODE == 3) ? ((int)gridDim.y - 1 - (int)blockIdx.y) : (int)blockIdx.y;
    const int m0 = my * BM;
    const int n0 = blockIdx.x * BN;
    if (MODE == 2 && n0 >= m0 + BM) return;     // fully-masked causal tile

    const __half* A = Ag + (size_t)blockIdx.z * sA;
    const __half* B = Bg + (size_t)blockIdx.z * sB;

    const int kEnd = (MODE == 3) ? (m0 + BM) : K_;
    const int NT   = kEnd / BKH;

    const uint32_t sbase = s2u(smem_raw);
    const int tid  = threadIdx.x;
    const int wid  = tid >> 5;
    const int lane = tid & 31;
    const int wm = (wid & 1) * 64;
    const int wn = (wid >> 1) * 32;
    const int g  = lane >> 2;
    const int tq = lane & 3;
    const int ld_r = tid >> 3;           // 0..31
    const int ld_c = (tid & 7) * 16;     // byte offset in 128B row
    const int ld_k = (tid & 7) * 8;      // half offset

    auto issue = [&](int kt) {
        if (kt < NT) {
            const uint32_t stage = sbase + (kt % STAGES) * STAGE_BYTES;
            const size_t kcol = (size_t)(kt * BKH + ld_k);
            #pragma unroll
            for (int j = 0; j < 4; j++) {
                const int row = ld_r + j * 32;
                cp16(stage + row * ROW_B + ld_c,           A + (size_t)(m0 + row) * K_ + kcol);
                cp16(stage + STAGE_A + row * ROW_B + ld_c, B + (size_t)(n0 + row) * K_ + kcol);
            }
        }
        CP_COMMIT();
    };

    issue(0);
    issue(1);

    float acc[4][4][4];
    #pragma unroll
    for (int i = 0; i < 4; i++)
        #pragma unroll
        for (int j = 0; j < 4; j++)
            #pragma unroll
            for (int r = 0; r < 4; r++) acc[i][j][r] = 0.f;

    const int l7 = lane & 7;
    const int sel = lane >> 3;

    for (int kt = 0; kt < NT; kt++) {
        CP_WAIT(STAGES - 2);
        __syncthreads();
        issue(kt + STAGES - 1);          // refill the slot all readers just left

        const uint32_t ab = sbase + (kt % STAGES) * STAGE_BYTES;
        const uint32_t bb = ab + STAGE_A;
        #pragma unroll
        for (int ks = 0; ks < 4; ks++) {
            uint32_t af[4][4], bf[4][2];
            #pragma unroll
            for (int mt = 0; mt < 4; mt++) {
                const int row = wm + mt * 16 + l7 + ((sel & 1) << 3);
                const int ch  = ks * 2 + (sel >> 1);
                ldmx4(af[mt], ab + row * ROW_B + ch * 16);
            }
            #pragma unroll
            for (int p = 0; p < 2; p++) {
                const int nrow = wn + p * 16 + ((sel >> 1) << 3) + l7;
                const int ch   = ks * 2 + (sel & 1);
                uint32_t r[4];
                ldmx4(r, bb + nrow * ROW_B + ch * 16);
                bf[p * 2][0]     = r[0]; bf[p * 2][1]     = r[1];
                bf[p * 2 + 1][0] = r[2]; bf[p * 2 + 1][1] = r[3];
            }
            #pragma unroll
            for (int mt = 0; mt < 4; mt++)
                #pragma unroll
                for (int nt = 0; nt < 4; nt++)
                    mma16816(acc[mt][nt], af[mt], bf[nt]);
        }
    }

    // ---------------- epilogue ----------------
    if (MODE == 4) {
        const int sector = n0 >> 10;
        const int nc0 = n0 & 1023;
        if (sector < 2) {
            __half* C = sector ? Ck : Cq;
            #pragma unroll
            for (int mt = 0; mt < 4; mt++) {
                const int r0 = m0 + wm + mt * 16 + g;
                #pragma unroll
                for (int nt = 0; nt < 4; nt++) {
                    const int c = nc0 + wn + nt * 8 + tq * 2;
                    *reinterpret_cast<__half2*>(C + (size_t)r0 * D_MODEL + c) =
                        __floats2half2_rn(acc[mt][nt][0], acc[mt][nt][1]);
                    *reinterpret_cast<__half2*>(C + (size_t)(r0 + 8) * D_MODEL + c) =
                        __floats2half2_rn(acc[mt][nt][2], acc[mt][nt][3]);
                }
            }
        } else {
            CP_WAIT(0);
            __syncthreads();
            __half* hbuf = reinterpret_cast<__half*>(smem_raw + wid * 4608);
            #pragma unroll
            for (int mt = 0; mt < 4; mt++) {
                const int t0 = mt * 16 + g;
                #pragma unroll
                for (int nt = 0; nt < 4; nt++) {
                    const int c = nt * 8 + tq * 2;
                    hbuf[(c    ) * 72 + t0    ] = __float2half_rn(acc[mt][nt][0]);
                    hbuf[(c + 1) * 72 + t0    ] = __float2half_rn(acc[mt][nt][1]);
                    hbuf[(c    ) * 72 + t0 + 8] = __float2half_rn(acc[mt][nt][2]);
                    hbuf[(c + 1) * 72 + t0 + 8] = __float2half_rn(acc[mt][nt][3]);
                }
            }
            __syncwarp();
            const int b = m0 >> 11;
            const int tok0 = (m0 & (SEQ - 1)) + wm;
            const int o = nc0 + wn + lane;
            const uint4* src = reinterpret_cast<const uint4*>(hbuf + lane * 72);
            uint4* dst = reinterpret_cast<uint4*>(Cvt + ((size_t)(b * D_MODEL + o)) * SEQ + tok0);
            #pragma unroll
            for (int u = 0; u < 8; u++) dst[u] = src[u];
        }
    } else {
        float* C = (float*)Cv + (size_t)blockIdx.z * sC;
        #pragma unroll
        for (int mt = 0; mt < 4; mt++) {
            const int r0 = m0 + wm + mt * 16 + g;
            #pragma unroll
            for (int nt = 0; nt < 4; nt++) {
                const int c = n0 + wn + nt * 8 + tq * 2;
                const float2 v0 = make_float2(acc[mt][nt][0] * scale, acc[mt][nt][1] * scale);
                const float2 v1 = make_float2(acc[mt][nt][2] * scale, acc[mt][nt][3] * scale);
                *reinterpret_cast<float2*>(C + (size_t)r0 * Ng + c) = v0;
                *reinterpret_cast<float2*>(C + (size_t)(r0 + 8) * Ng + c) = v1;
            }
        }
    }
}

// ---------------- fp32 -> fp16 conversion ----------------
__global__ void __launch_bounds__(256) f2h(const float4* __restrict__ s,
                                           __half2* __restrict__ d, int n4)
{
    const int i = blockIdx.x * blockDim.x + threadIdx.x;
    if (i < n4) {
        const float4 v = s[i];
        d[2 * i]     = __floats2half2_rn(v.x, v.y);
        d[2 * i + 1] = __floats2half2_rn(v.z, v.w);
    }
}

// ---------------- causal softmax: S fp32 -> P fp16 ----------------
__global__ void __launch_bounds__(256) softmax_causal(const float* __restrict__ S,
                                                      __half* __restrict__ P)
{
    __shared__ float red[8];
    const int row = blockIdx.x;
    const int i   = row & (SEQ - 1);
    const int L   = i + 1;
    const int Wl  = (i | 127) + 1;     // zero-fill to the 128-block edge only
    const float* s = S + (size_t)row * SEQ;
    __half* p = P + (size_t)row * SEQ;
    const int tid = threadIdx.x;

    float v[SEQ / 256];
    float m = -3.4e38f;
    #pragma unroll
    for (int it = 0; it < SEQ / 256; it++) {
        const int j = tid + it * 256;
        v[it] = (j < L) ? s[j] : -3.4e38f;
        m = fmaxf(m, v[it]);
    }
    #pragma unroll
    for (int o = 16; o; o >>= 1) m = fmaxf(m, __shfl_xor_sync(0xffffffffu, m, o));
    if ((tid & 31) == 0) red[tid >> 5] = m;
    __syncthreads();
    m = red[0];
    #pragma unroll
    for (int w = 1; w < 8; w++) m = fmaxf(m, red[w]);
    __syncthreads();

    float sum = 0.f;
    #pragma unroll
    for (int it = 0; it < SEQ / 256; it++) {
        const int j = tid + it * 256;
        const float e = (j < L) ? __expf(v[it] - m) : 0.f;
        v[it] = e;
        sum += e;
    }
    #pragma unroll
    for (int o = 16; o; o >>= 1) sum += __shfl_xor_sync(0xffffffffu, sum, o);
    if ((tid & 31) == 0) red[tid >> 5] = sum;
    __syncthreads();
    sum = 0.f;
    #pragma unroll
    for (int w = 0; w < 8; w++) sum += red[w];
    const float inv = 1.f / sum;

    #pragma unroll
    for (int it = 0; it < SEQ / 256; it++) {
        const int j = tid + it * 256;
        if (j < Wl) p[j] = __float2half_rn(v[it] * inv);
    }
}

// ---------------- launch ----------------
extern "C" void kernel_launch(void* const* d_in, const int* in_sizes, int n_in,
                              void* d_out, int out_size)
{
    const float* x  = (const float*)d_in[0];
    const float* Wq = (const float*)d_in[1];
    const float* Wk = (const float*)d_in[2];
    const float* Wv = (const float*)d_in[3];
    float* out = (float*)d_out;

    __half *pxh, *pWh, *pQh, *pKh, *pVth, *pP;
    float *pS;
    cudaGetSymbolAddress((void**)&pxh,  g_xh);
    cudaGetSymbolAddress((void**)&pWh,  g_Wh);
    cudaGetSymbolAddress((void**)&pQh,  g_Qh);
    cudaGetSymbolAddress((void**)&pKh,  g_Kh);
    cudaGetSymbolAddress((void**)&pVth, g_Vth);
    cudaGetSymbolAddress((void**)&pS,   g_S);
    cudaGetSymbolAddress((void**)&pP,   g_P);

    cudaFuncSetAttribute(gemm_h<4>, cudaFuncAttributeMaxDynamicSharedMemorySize, SMEM_TOTAL);
    cudaFuncSetAttribute(gemm_h<2>, cudaFuncAttributeMaxDynamicSharedMemorySize, SMEM_TOTAL);
    cudaFuncSetAttribute(gemm_h<3>, cudaFuncAttributeMaxDynamicSharedMemorySize, SMEM_TOTAL);

    const int WSZ = D_MODEL * D_MODEL;

    // 0) fp32 -> fp16 conversions
    {
        const int n4 = NROWS * D_MODEL / 4;
        const int w4 = WSZ / 4;
        f2h<<<(n4 + 255) / 256, 256>>>((const float4*)x, (__half2*)pxh, n4);
        f2h<<<(w4 + 255) / 256, 256>>>((const float4*)Wq, (__half2*)pWh, w4);
        f2h<<<(w4 + 255) / 256, 256>>>((const float4*)Wk, (__half2*)(pWh + WSZ), w4);
        f2h<<<(w4 + 255) / 256, 256>>>((const float4*)Wv, (__half2*)(pWh + 2 * WSZ), w4);
    }

    const dim3 blk(256);

    // 1) fused QKV projection
    {
        dim3 grid(3 * D_MODEL / BN, NROWS / BM, 1);
        gemm_h<4><<<grid, blk, SMEM_TOTAL>>>(pxh, pWh, nullptr, D_MODEL, 3 * D_MODEL,
                                             0, 0, 0, 1.f, pQh, pKh, pVth);
    }

    // 2) S = (Q @ K^T) / 32, causal tile skip
    {
        dim3 grid(SEQ / BN, SEQ / BM, BATCH);
        gemm_h<2><<<grid, blk, SMEM_TOTAL>>>(pQh, pKh, pS, D_MODEL, SEQ,
                                             (long long)SEQ * D_MODEL,
                                             (long long)SEQ * D_MODEL,
                                             (long long)SEQ * SEQ, 0.03125f,
                                             nullptr, nullptr, nullptr);
    }

    // 3) causal softmax: S fp32 -> P fp16
    softmax_causal<<<NROWS, 256>>>(pS, pP);

    // 4) O = P @ Vt^T, K truncated per block-row, longest m-tiles first
    {
        dim3 grid(D_MODEL / BN, SEQ / BM, BATCH);
        gemm_h<3><<<grid, blk, SMEM_TOTAL>>>(pP, pVth, out, SEQ, D_MODEL,
                                             (long long)SEQ * SEQ,
                                             (long long)D_MODEL * SEQ,
                                             (long long)SEQ * D_MODEL, 1.f,
                                             nullptr, nullptr, nullptr);
    }
}

// round 14
// speedup vs baseline: 2.8302x; 1.0100x over previous
#include <cuda_runtime.h>
#include <cuda_fp16.h>
#include <cstdint>

#define D_MODEL 1024
#define BATCH   8
#define SEQ     2048
#define NROWS   (BATCH * SEQ)   /* total query rows */

// ---------------- scratch (static device globals; no allocation anywhere) ----------------
__device__ __half g_xh [(size_t)NROWS * D_MODEL];
__device__ __half g_Wh [(size_t)3 * D_MODEL * D_MODEL];      // packed [Wq;Wk;Wv]
__device__ __half g_Qh [(size_t)NROWS * D_MODEL];
__device__ __half g_Kh [(size_t)NROWS * D_MODEL];
__device__ __half g_Vth[(size_t)BATCH * D_MODEL * SEQ];      // V transposed: [b][o][tok]
__device__ float  g_S  [(size_t)BATCH * SEQ * SEQ];
__device__ __half g_P  [(size_t)BATCH * SEQ * SEQ];

// ------ tiling: 128x128 CTA, 256 threads, 2 CTAs/SM, 64-half (128B) k-tiles ------
#define BM 128
#define BN 128
#define BKH 64
#define STAGES 3
#define ROW_B 144       /* 128B data + 16B pad; stride 36 banks => conflict-free ldmatrix */
#define STAGE_A (BM * ROW_B)
#define STAGE_B (BN * ROW_B)
#define STAGE_BYTES (STAGE_A + STAGE_B)
#define SMEM_TOTAL (STAGES * STAGE_BYTES)   /* 110592 B per CTA -> 2 CTAs/SM */

// ---------------- ptx helpers ----------------
__device__ __forceinline__ uint32_t s2u(const void* p) {
    uint32_t a;
    asm("{ .reg .u64 t; cvta.to.shared.u64 t, %1; cvt.u32.u64 %0, t; }" : "=r"(a) : "l"(p));
    return a;
}
__device__ __forceinline__ void cp16(uint32_t dst, const void* src) {
    asm volatile("cp.async.cg.shared.global [%0], [%1], 16;" :: "r"(dst), "l"(src));
}
#define CP_COMMIT() asm volatile("cp.async.commit_group;" ::: "memory")
#define CP_WAIT(n)  asm volatile("cp.async.wait_group %0;" :: "n"(n) : "memory")

__device__ __forceinline__ void ldmx4(uint32_t* r, uint32_t a) {
    asm volatile("ldmatrix.sync.aligned.m8n8.x4.shared.b16 {%0,%1,%2,%3}, [%4];"
        : "=r"(r[0]), "=r"(r[1]), "=r"(r[2]), "=r"(r[3]) : "r"(a));
}
__device__ __forceinline__ void mma16816(float* c, const uint32_t* a, const uint32_t* b) {
    asm volatile(
        "mma.sync.aligned.m16n8k16.row.col.f32.f16.f16.f32 "
        "{%0,%1,%2,%3},{%4,%5,%6,%7},{%8,%9},{%0,%1,%2,%3};"
        : "+f"(c[0]), "+f"(c[1]), "+f"(c[2]), "+f"(c[3])
        : "r"(a[0]), "r"(a[1]), "r"(a[2]), "r"(a[3]), "r"(b[0]), "r"(b[1]));
}

// ---------------- fp16 NT GEMM:  C = scale * A @ B^T ----------------
// MODE 4: fused QKV (N=3072, epilogue routes sector 0/1 -> Q/K plain, 2 -> Vt transposed)
// MODE 2: S gemm (fp32 out * scale; tiles fully above the causal diagonal skipped)
// MODE 3: PV gemm (fp32 out; K truncated at m0+BM; longest m-tiles scheduled first)
template<int MODE>
__global__ void __launch_bounds__(256, 2)
gemm_h(const __half* __restrict__ Ag, const __half* __restrict__ Bg, void* __restrict__ Cv,
       int K_, int Ng, long long sA, long long sB, long long sC, float scale,
       __half* __restrict__ Cq, __half* __restrict__ Ck, __half* __restrict__ Cvt)
{
    extern __shared__ char smem_raw[];
    const int my = (MODE == 3) ? ((int)gridDim.y - 1 - (int)blockIdx.y) : (int)blockIdx.y;
    const int m0 = my * BM;
    const int n0 = blockIdx.x * BN;
    if (MODE == 2 && n0 >= m0 + BM) return;

    const __half* A = Ag + (size_t)blockIdx.z * sA;
    const __half* B = Bg + (size_t)blockIdx.z * sB;

    const int kEnd = (MODE == 3) ? (m0 + BM) : K_;
    const int NT   = kEnd / BKH;

    const uint32_t sbase = s2u(smem_raw);
    const int tid  = threadIdx.x;
    const int wid  = tid >> 5;
    const int lane = tid & 31;
    const int wm = (wid & 1) * 64;
    const int wn = (wid >> 1) * 32;
    const int g  = lane >> 2;
    const int tq = lane & 3;
    const int ld_r = tid >> 3;
    const int ld_c = (tid & 7) * 16;
    const int ld_k = (tid & 7) * 8;

    auto issue = [&](int kt) {
        if (kt < NT) {
            const uint32_t stage = sbase + (kt % STAGES) * STAGE_BYTES;
            const size_t kcol = (size_t)(kt * BKH + ld_k);
            #pragma unroll
            for (int j = 0; j < 4; j++) {
                const int row = ld_r + j * 32;
                cp16(stage + row * ROW_B + ld_c,           A + (size_t)(m0 + row) * K_ + kcol);
                cp16(stage + STAGE_A + row * ROW_B + ld_c, B + (size_t)(n0 + row) * K_ + kcol);
            }
        }
        CP_COMMIT();
    };

    issue(0);
    issue(1);

    float acc[4][4][4];
    #pragma unroll
    for (int i = 0; i < 4; i++)
        #pragma unroll
        for (int j = 0; j < 4; j++)
            #pragma unroll
            for (int r = 0; r < 4; r++) acc[i][j][r] = 0.f;

    const int l7 = lane & 7;
    const int sel = lane >> 3;

    for (int kt = 0; kt < NT; kt++) {
        CP_WAIT(STAGES - 2);
        __syncthreads();
        issue(kt + STAGES - 1);

        const uint32_t ab = sbase + (kt % STAGES) * STAGE_BYTES;
        const uint32_t bb = ab + STAGE_A;
        #pragma unroll
        for (int ks = 0; ks < 4; ks++) {
            uint32_t af[4][4], bf[4][2];
            #pragma unroll
            for (int mt = 0; mt < 4; mt++) {
                const int row = wm + mt * 16 + l7 + ((sel & 1) << 3);
                const int ch  = ks * 2 + (sel >> 1);
                ldmx4(af[mt], ab + row * ROW_B + ch * 16);
            }
            #pragma unroll
            for (int p = 0; p < 2; p++) {
                const int nrow = wn + p * 16 + ((sel >> 1) << 3) + l7;
                const int ch   = ks * 2 + (sel & 1);
                uint32_t r[4];
                ldmx4(r, bb + nrow * ROW_B + ch * 16);
                bf[p * 2][0]     = r[0]; bf[p * 2][1]     = r[1];
                bf[p * 2 + 1][0] = r[2]; bf[p * 2 + 1][1] = r[3];
            }
            #pragma unroll
            for (int mt = 0; mt < 4; mt++)
                #pragma unroll
                for (int nt = 0; nt < 4; nt++)
                    mma16816(acc[mt][nt], af[mt], bf[nt]);
        }
    }

    // ---------------- epilogue ----------------
    if (MODE == 4) {
        const int sector = n0 >> 10;
        const int nc0 = n0 & 1023;
        if (sector < 2) {
            __half* C = sector ? Ck : Cq;
            #pragma unroll
            for (int mt = 0; mt < 4; mt++) {
                const int r0 = m0 + wm + mt * 16 + g;
                #pragma unroll
                for (int nt = 0; nt < 4; nt++) {
                    const int c = nc0 + wn + nt * 8 + tq * 2;
                    *reinterpret_cast<__half2*>(C + (size_t)r0 * D_MODEL + c) =
                        __floats2half2_rn(acc[mt][nt][0], acc[mt][nt][1]);
                    *reinterpret_cast<__half2*>(C + (size_t)(r0 + 8) * D_MODEL + c) =
                        __floats2half2_rn(acc[mt][nt][2], acc[mt][nt][3]);
                }
            }
        } else {
            CP_WAIT(0);
            __syncthreads();
            __half* hbuf = reinterpret_cast<__half*>(smem_raw + wid * 4608);
            #pragma unroll
            for (int mt = 0; mt < 4; mt++) {
                const int t0 = mt * 16 + g;
                #pragma unroll
                for (int nt = 0; nt < 4; nt++) {
                    const int c = nt * 8 + tq * 2;
                    hbuf[(c    ) * 72 + t0    ] = __float2half_rn(acc[mt][nt][0]);
                    hbuf[(c + 1) * 72 + t0    ] = __float2half_rn(acc[mt][nt][1]);
                    hbuf[(c    ) * 72 + t0 + 8] = __float2half_rn(acc[mt][nt][2]);
                    hbuf[(c + 1) * 72 + t0 + 8] = __float2half_rn(acc[mt][nt][3]);
                }
            }
            __syncwarp();
            const int b = m0 >> 11;
            const int tok0 = (m0 & (SEQ - 1)) + wm;
            const int o = nc0 + wn + lane;
            const uint4* src = reinterpret_cast<const uint4*>(hbuf + lane * 72);
            uint4* dst = reinterpret_cast<uint4*>(Cvt + ((size_t)(b * D_MODEL + o)) * SEQ + tok0);
            #pragma unroll
            for (int u = 0; u < 8; u++) dst[u] = src[u];
        }
    } else {
        float* C = (float*)Cv + (size_t)blockIdx.z * sC;
        #pragma unroll
        for (int mt = 0; mt < 4; mt++) {
            const int r0 = m0 + wm + mt * 16 + g;
            #pragma unroll
            for (int nt = 0; nt < 4; nt++) {
                const int c = n0 + wn + nt * 8 + tq * 2;
                const float2 v0 = make_float2(acc[mt][nt][0] * scale, acc[mt][nt][1] * scale);
                const float2 v1 = make_float2(acc[mt][nt][2] * scale, acc[mt][nt][3] * scale);
                *reinterpret_cast<float2*>(C + (size_t)r0 * Ng + c) = v0;
                *reinterpret_cast<float2*>(C + (size_t)(r0 + 8) * Ng + c) = v1;
            }
        }
    }
}

// -------- merged weight fp32 -> fp16 conversion: all three matrices, one launch --------
__global__ void __launch_bounds__(256) f2h_w3(const float4* __restrict__ w0,
                                              const float4* __restrict__ w1,
                                              const float4* __restrict__ w2,
                                              __half2* __restrict__ d, int n4seg)
{
    const int i = blockIdx.x * blockDim.x + threadIdx.x;   // grid covers 3*n4seg exactly
    const int seg = i / n4seg;
    const int idx = i - seg * n4seg;
    const float4* s = (seg == 0) ? w0 : (seg == 1) ? w1 : w2;
    const float4 v = s[idx];
    __half2* dd = d + (size_t)seg * n4seg * 2;
    dd[2 * idx]     = __floats2half2_rn(v.x, v.y);
    dd[2 * idx + 1] = __floats2half2_rn(v.z, v.w);
}

// ---------------- fp32 -> fp16 conversion for x ----------------
__global__ void __launch_bounds__(256) f2h(const float4* __restrict__ s,
                                           __half2* __restrict__ d, int n4)
{
    const int i = blockIdx.x * blockDim.x + threadIdx.x;
    if (i < n4) {
        const float4 v = s[i];
        d[2 * i]     = __floats2half2_rn(v.x, v.y);
        d[2 * i + 1] = __floats2half2_rn(v.z, v.w);
    }
}

// ---------------- causal softmax: S fp32 -> P fp16, float2/half2 vectorized ----------------
__global__ void __launch_bounds__(256) softmax_causal(const float* __restrict__ S,
                                                      __half* __restrict__ P)
{
    __shared__ float red[8];
    const int row = blockIdx.x;
    const int i   = row & (SEQ - 1);
    const int L   = i + 1;
    const int Wl  = (i | 127) + 1;     // fill to 128-block edge; always even
    const float* s = S + (size_t)row * SEQ;
    __half* p = P + (size_t)row * SEQ;
    const int tid = threadIdx.x;

    float2 v[4];
    float m = -3.4e38f;
    #pragma unroll
    for (int it = 0; it < 4; it++) {
        const int j2 = (tid + it * 256) * 2;
        float2 val = *reinterpret_cast<const float2*>(s + j2);  // in-bounds; finite beyond L
        val.x = (j2     < L) ? val.x : -3.4e38f;
        val.y = (j2 + 1 < L) ? val.y : -3.4e38f;
        v[it] = val;
        m = fmaxf(m, fmaxf(val.x, val.y));
    }
    #pragma unroll
    for (int o = 16; o; o >>= 1) m = fmaxf(m, __shfl_xor_sync(0xffffffffu, m, o));
    if ((tid & 31) == 0) red[tid >> 5] = m;
    __syncthreads();
    m = red[0];
    #pragma unroll
    for (int w = 1; w < 8; w++) m = fmaxf(m, red[w]);
    __syncthreads();

    float sum = 0.f;
    #pragma unroll
    for (int it = 0; it < 4; it++) {
        const int j2 = (tid + it * 256) * 2;
        const float ex = (j2     < L) ? __expf(v[it].x - m) : 0.f;
        const float ey = (j2 + 1 < L) ? __expf(v[it].y - m) : 0.f;
        v[it].x = ex; v[it].y = ey;
        sum += ex + ey;
    }
    #pragma unroll
    for (int o = 16; o; o >>= 1) sum += __shfl_xor_sync(0xffffffffu, sum, o);
    if ((tid & 31) == 0) red[tid >> 5] = sum;
    __syncthreads();
    sum = 0.f;
    #pragma unroll
    for (int w = 0; w < 8; w++) sum += red[w];
    const float inv = 1.f / sum;

    #pragma unroll
    for (int it = 0; it < 4; it++) {
        const int j2 = (tid + it * 256) * 2;
        if (j2 < Wl)
            *reinterpret_cast<__half2*>(p + j2) =
                __floats2half2_rn(v[it].x * inv, v[it].y * inv);
    }
}

// ---------------- launch ----------------
extern "C" void kernel_launch(void* const* d_in, const int* in_sizes, int n_in,
                              void* d_out, int out_size)
{
    const float* x  = (const float*)d_in[0];
    const float* Wq = (const float*)d_in[1];
    const float* Wk = (const float*)d_in[2];
    const float* Wv = (const float*)d_in[3];
    float* out = (float*)d_out;

    __half *pxh, *pWh, *pQh, *pKh, *pVth, *pP;
    float *pS;
    cudaGetSymbolAddress((void**)&pxh,  g_xh);
    cudaGetSymbolAddress((void**)&pWh,  g_Wh);
    cudaGetSymbolAddress((void**)&pQh,  g_Qh);
    cudaGetSymbolAddress((void**)&pKh,  g_Kh);
    cudaGetSymbolAddress((void**)&pVth, g_Vth);
    cudaGetSymbolAddress((void**)&pS,   g_S);
    cudaGetSymbolAddress((void**)&pP,   g_P);

    cudaFuncSetAttribute(gemm_h<4>, cudaFuncAttributeMaxDynamicSharedMemorySize, SMEM_TOTAL);
    cudaFuncSetAttribute(gemm_h<2>, cudaFuncAttributeMaxDynamicSharedMemorySize, SMEM_TOTAL);
    cudaFuncSetAttribute(gemm_h<3>, cudaFuncAttributeMaxDynamicSharedMemorySize, SMEM_TOTAL);

    const int WSZ = D_MODEL * D_MODEL;

    // 0) conversions: one merged weight launch + x
    {
        const int w4 = WSZ / 4;
        f2h_w3<<<3 * w4 / 256, 256>>>((const float4*)Wq, (const float4*)Wk,
                                      (const float4*)Wv, (__half2*)pWh, w4);
        const int n4 = NROWS * D_MODEL / 4;
        f2h<<<(n4 + 255) / 256, 256>>>((const float4*)x, (__half2*)pxh, n4);
    }

    const dim3 blk(256);

    // 1) fused QKV projection
    {
        dim3 grid(3 * D_MODEL / BN, NROWS / BM, 1);
        gemm_h<4><<<grid, blk, SMEM_TOTAL>>>(pxh, pWh, nullptr, D_MODEL, 3 * D_MODEL,
                                             0, 0, 0, 1.f, pQh, pKh, pVth);
    }

    // 2) S = (Q @ K^T) / 32, causal tile skip
    {
        dim3 grid(SEQ / BN, SEQ / BM, BATCH);
        gemm_h<2><<<grid, blk, SMEM_TOTAL>>>(pQh, pKh, pS, D_MODEL, SEQ,
                                             (long long)SEQ * D_MODEL,
                                             (long long)SEQ * D_MODEL,
                                             (long long)SEQ * SEQ, 0.03125f,
                                             nullptr, nullptr, nullptr);
    }

    // 3) causal softmax: S fp32 -> P fp16
    softmax_causal<<<NROWS, 256>>>(pS, pP);

    // 4) O = P @ Vt^T, K truncated per block-row, longest m-tiles first
    {
        dim3 grid(D_MODEL / BN, SEQ / BM, BATCH);
        gemm_h<3><<<grid, blk, SMEM_TOTAL>>>(pP, pVth, out, SEQ, D_MODEL,
                                             (long long)SEQ * SEQ,
                                             (long long)D_MODEL * SEQ,
                                             (long long)SEQ * D_MODEL, 1.f,
                                             nullptr, nullptr, nullptr);
    }
}